// round 8
// baseline (speedup 1.0000x reference)
#include <cuda_runtime.h>
#include <cuda_bf16.h>
#include <cstdint>

#define B_DIM 32
#define C_DIM 512
#define N_DIM 1024   // H*W

// ---------------- device scratch (allocation-free) --------------------------
__device__ __align__(16) unsigned short g_wvh[64 * 512];    // Wv^T hi  [d][c]
__device__ __align__(16) unsigned short g_wvl[64 * 512];    // Wv^T lo
__device__ __align__(16) unsigned short g_wph[512 * 512];   // Wp^T hi  [c2][c]
__device__ __align__(16) unsigned short g_wpl[512 * 512];   // Wp^T lo
__device__ float g_bv[64];
__device__ __align__(16) unsigned g_vh[B_DIM * 1024 * 32];  // v hi bf16 pairs [b][n][d/2]
__device__ __align__(16) unsigned g_vl[B_DIM * 1024 * 32];  // v lo

// ---------------- helpers ----------------------------------------------------
__device__ __forceinline__ unsigned smem_u32(const void* p) {
    unsigned a;
    asm("{ .reg .u64 t; cvta.to.shared.u64 t, %1; cvt.u32.u64 %0, t; }" : "=r"(a) : "l"(p));
    return a;
}
__device__ __forceinline__ void ldm_x4(unsigned* d, unsigned addr) {
    asm volatile("ldmatrix.sync.aligned.m8n8.x4.shared.b16 {%0,%1,%2,%3}, [%4];"
                 : "=r"(d[0]), "=r"(d[1]), "=r"(d[2]), "=r"(d[3]) : "r"(addr));
}
__device__ __forceinline__ void mma_bf16(float* c, const unsigned* a, const unsigned* b) {
    asm volatile(
        "mma.sync.aligned.m16n8k16.row.col.f32.bf16.bf16.f32 "
        "{%0,%1,%2,%3}, {%4,%5,%6,%7}, {%8,%9}, {%0,%1,%2,%3};"
        : "+f"(c[0]), "+f"(c[1]), "+f"(c[2]), "+f"(c[3])
        : "r"(a[0]), "r"(a[1]), "r"(a[2]), "r"(a[3]), "r"(b[0]), "r"(b[1]));
}
__device__ __forceinline__ void cp16(unsigned dst, const void* src) {
    asm volatile("cp.async.cg.shared.global [%0], [%1], 16;" :: "r"(dst), "l"(src));
}
__device__ __forceinline__ void cp_commit() { asm volatile("cp.async.commit_group;" ::: "memory"); }
__device__ __forceinline__ void cp_wait0()  { asm volatile("cp.async.wait_group 0;" ::: "memory"); }

__device__ __forceinline__ void cvt_split_pair(float f0, float f1, unsigned& h, unsigned& l) {
    asm("cvt.rn.bf16x2.f32 %0, %1, %2;" : "=r"(h) : "f"(f1), "f"(f0));
    float r0 = f0 - __uint_as_float(h << 16);
    float r1 = f1 - __uint_as_float(h & 0xffff0000u);
    asm("cvt.rn.bf16x2.f32 %0, %1, %2;" : "=r"(l) : "f"(r1), "f"(r0));
}

// ---------------------------------------------------------------------------
// prep (single launch): blocks [0,128) -> Wv^T split + bias; [128,384) -> Wp^T
// ---------------------------------------------------------------------------
__global__ void prep_all(const float* __restrict__ Wqkv, const float* __restrict__ bqkv,
                         const float* __restrict__ Wp) {
    int bid = blockIdx.x, tid = threadIdx.x;
    if (bid < 128) {
        int idx = bid * 256 + tid;                 // 32768
        int d = idx & 63, c = idx >> 6;
        const float* p = Wqkv + (size_t)c * 1536 + 1024 + d;
        float s = 0.f;
        #pragma unroll
        for (int h = 0; h < 8; ++h) s += p[h * 64];
        s *= 0.125f;
        __nv_bfloat16 hi = __float2bfloat16(s);
        __nv_bfloat16 lo = __float2bfloat16(s - __bfloat162float(hi));
        g_wvh[d * 512 + c] = *(unsigned short*)&hi;
        g_wvl[d * 512 + c] = *(unsigned short*)&lo;
        if (idx < 64) {
            float t = 0.f;
            #pragma unroll
            for (int h = 0; h < 8; ++h) t += bqkv[1024 + h * 64 + idx];
            g_bv[idx] = t * 0.125f;
        }
    } else {
        __shared__ float th[32][33], tl[32][33];
        int t = bid - 128;                          // 256 tiles
        int c0 = (t & 15) * 32, c20 = (t >> 4) * 32;
        int tx = tid & 31, ty = tid >> 5;           // (32, 8)
        #pragma unroll
        for (int i = 0; i < 4; ++i) {
            int c = c0 + ty + i * 8;
            float s = Wp[(size_t)c * 512 + c20 + tx];
            float hi = __bfloat162float(__float2bfloat16(s));
            th[ty + i * 8][tx] = hi;
            tl[ty + i * 8][tx] = s - hi;
        }
        __syncthreads();
        #pragma unroll
        for (int i = 0; i < 4; ++i) {
            int c2 = c20 + ty + i * 8;
            __nv_bfloat16 hb = __float2bfloat16(th[tx][ty + i * 8]);
            __nv_bfloat16 lb = __float2bfloat16(tl[tx][ty + i * 8]);
            g_wph[(size_t)c2 * 512 + c0 + tx] = *(unsigned short*)&hb;
            g_wpl[(size_t)c2 * 512 + c0 + tx] = *(unsigned short*)&lb;
        }
    }
}

// ---------------- warp MMA fragment offsets ---------------------------------
struct Frag { unsigned aoff[2]; unsigned boff[2]; };

// Separate pitches for A and B regions
template<int PITCHA, int PITCHB>
__device__ __forceinline__ Frag make_frag2(int lane, int mw, int nw, unsigned off_b) {
    Frag fr;
    const int j4 = lane >> 3, r8 = lane & 7;
    #pragma unroll
    for (int mi = 0; mi < 2; ++mi)
        fr.aoff[mi] = (mw * 32 + mi * 16 + (j4 & 1) * 8 + r8) * PITCHA + (j4 >> 1) * 16;
    const int g2 = (lane >> 4) & 1, c8 = (lane >> 3) & 1;
    #pragma unroll
    for (int j2 = 0; j2 < 2; ++j2)
        fr.boff[j2] = off_b + (nw * 32 + j2 * 16 + g2 * 8 + r8) * PITCHB + c8 * 16;
    return fr;
}

// MMA over KS k-slices; A from baseA+aoff, B from baseB+boff
template<int KS, int AL, int BL>
__device__ __forceinline__ void mma_stage2(unsigned baseA, unsigned baseB,
                                           const Frag& fr, float C[2][4][4]) {
    #pragma unroll
    for (int ks = 0; ks < KS; ++ks) {
        unsigned ah[2][4], al[2][4], bh[2][4], bl[2][4];
        #pragma unroll
        for (int mi = 0; mi < 2; ++mi) {
            ldm_x4(ah[mi], baseA + fr.aoff[mi] + ks * 32);
            ldm_x4(al[mi], baseA + fr.aoff[mi] + ks * 32 + AL);
        }
        #pragma unroll
        for (int j2 = 0; j2 < 2; ++j2) {
            ldm_x4(bh[j2], baseB + fr.boff[j2] + ks * 32);
            ldm_x4(bl[j2], baseB + fr.boff[j2] + ks * 32 + BL);
        }
        #pragma unroll
        for (int mi = 0; mi < 2; ++mi)
            #pragma unroll
            for (int ni = 0; ni < 4; ++ni) {
                const unsigned* bhp = &bh[ni >> 1][(ni & 1) * 2];
                const unsigned* blp = &bl[ni >> 1][(ni & 1) * 2];
                mma_bf16(C[mi][ni], ah[mi], bhp);
                mma_bf16(C[mi][ni], ah[mi], blp);
                mma_bf16(C[mi][ni], al[mi], bhp);
            }
    }
}

// ---------------------------------------------------------------------------
// GEMM1: tile 256(n) x 64(d), 512 thr (16 warps: 8m x 2n), K-chunk 32, 16 chunks
// A: 2 stages, pitch 80B (stage 40960B). B: RESIDENT full K=512, pitch 1040B.
// smem: A stage0 [0,40960) | A stage1 [40960,81920) | Bh [81920, +66560) | Bl
// ---------------------------------------------------------------------------
#define G1_AL   20480                 // lo offset within A stage
#define G1_ASTG 40960                 // A stage stride
#define G1_BOFF 81920                 // B region base
#define G1_BPITCH 1040                // B row pitch (512 halves + 8 pad)
#define G1_BL   66560                 // lo offset within B region (64*1040)
#define G1_SMEM (81920 + 2 * 66560)   // 215040

__global__ void __launch_bounds__(512) gemm1_mma(const float* __restrict__ x) {
    extern __shared__ char smem[];
    const int tid = threadIdx.x, lane = tid & 31, wid = tid >> 5;
    const int mw = wid >> 1, nw = wid & 1;
    const int b = blockIdx.y, n0 = blockIdx.x * 256;
    const unsigned sb = smem_u32(smem);
    const Frag fr = make_frag2<80, G1_BPITCH>(lane, mw, nw, G1_BOFF);

    const int m_ld = tid & 255, kb0 = tid >> 8;        // A convert: kblock = kb0 + 2i
    const float* xb = x + (size_t)b * (C_DIM * N_DIM) + n0;

    float C[2][4][4] = {};
    float f[2][8];

    auto ldg_chunk = [&](int kc) {
        const float* xc = xb + (size_t)kc * 32 * N_DIM;
        #pragma unroll
        for (int i = 0; i < 2; ++i) {
            int k0 = (kb0 + 2 * i) * 8;
            #pragma unroll
            for (int j = 0; j < 8; ++j)
                f[i][j] = xc[(size_t)(k0 + j) * N_DIM + m_ld];
        }
    };
    auto cvt_sts = [&](int st) {
        char* base = smem + st * G1_ASTG;
        #pragma unroll
        for (int i = 0; i < 2; ++i) {
            unsigned h[4], l[4];
            #pragma unroll
            for (int p = 0; p < 4; ++p)
                cvt_split_pair(f[i][2 * p], f[i][2 * p + 1], h[p], l[p]);
            unsigned off = m_ld * 80 + (kb0 + 2 * i) * 16;
            *(uint4*)(base + off) = make_uint4(h[0], h[1], h[2], h[3]);
            *(uint4*)(base + G1_AL + off) = make_uint4(l[0], l[1], l[2], l[3]);
        }
    };

    // prologue: full resident B via one cp.async group; A chunk 0 staged; chunk 1 in regs
    ldg_chunk(0);
    #pragma unroll
    for (int i = 0; i < 8; ++i) {
        int idx = tid + i * 512;                   // 0..4095
        int r = idx >> 6, q = idx & 63;            // 64 rows x 64 quads
        size_t s = (size_t)r * 512 + q * 8;
        unsigned doff = sb + G1_BOFF + r * G1_BPITCH + q * 16;
        cp16(doff, g_wvh + s);
        cp16(doff + G1_BL, g_wvl + s);
    }
    cp_commit();
    cvt_sts(0);
    ldg_chunk(1);
    cp_wait0();
    __syncthreads();

    for (int kc = 0; kc < 16; ++kc) {
        const int st = kc & 1, nst = st ^ 1;
        if (kc < 15) cvt_sts(nst);
        if (kc < 14) ldg_chunk(kc + 2);
        mma_stage2<2, G1_AL, G1_BL>(sb + st * G1_ASTG, sb + kc * 64, fr, C);
        __syncthreads();
    }

    // epilogue: add bias, split, store v
    const int gr = lane >> 2, gc2 = (lane & 3) * 2;
    #pragma unroll
    for (int mi = 0; mi < 2; ++mi) {
        int m = n0 + mw * 32 + mi * 16 + gr;
        unsigned base0 = (unsigned)(b * 1024 + m) * 32u;
        unsigned base1 = base0 + 8 * 32;
        #pragma unroll
        for (int ni = 0; ni < 4; ++ni) {
            int d = nw * 32 + ni * 8 + gc2;
            float bv0 = g_bv[d], bv1 = g_bv[d + 1];
            unsigned h, l;
            cvt_split_pair(C[mi][ni][0] + bv0, C[mi][ni][1] + bv1, h, l);
            g_vh[base0 + (d >> 1)] = h;
            g_vl[base0 + (d >> 1)] = l;
            cvt_split_pair(C[mi][ni][2] + bv0, C[mi][ni][3] + bv1, h, l);
            g_vh[base1 + (d >> 1)] = h;
            g_vl[base1 + (d >> 1)] = l;
        }
    }
}

// ---------------------------------------------------------------------------
// GEMM2: tile 128(r) x 128(c2), 512 thr (16 warps: 4m x 4n), K-chunk 64, 8 chunks
// 2 stages, pitch 144B. stage: Ah 128*144=18432 | Al | Bh | Bl -> 73728
// (byte-identical to round-6 config)
// ---------------------------------------------------------------------------
#define G2_AL 18432
#define G2_B  36864
#define G2_BL 18432
#define G2_STG 73728
#define G2_SMEM (2 * G2_STG)

__global__ void __launch_bounds__(512) gemm2_mma(const float* __restrict__ bp,
                                                 float* __restrict__ out) {
    extern __shared__ char smem[];
    const int tid = threadIdx.x, lane = tid & 31, wid = tid >> 5;
    const int mw = wid >> 2, nw = wid & 3;
    const int b = blockIdx.y, c20 = blockIdx.x * 128;
    const unsigned sb = smem_u32(smem);
    const Frag fr = make_frag2<144, 144>(lane, mw, nw, G2_B);

    const unsigned short* vhb = (const unsigned short*)g_vh + (size_t)b * 65536;
    const unsigned short* vlb = (const unsigned short*)g_vl + (size_t)b * 65536;

    float C[2][4][4] = {};

    auto issue = [&](int kc, int st) {
        unsigned stb = sb + st * G2_STG;
        #pragma unroll
        for (int i = 0; i < 2; ++i) {
            int idx = tid * 2 + i;                 // 0..1023
            int r = idx >> 3, q = idx & 7;
            size_t s = (size_t)r * 512 + kc * 64 + q * 8;
            unsigned off = r * 144 + q * 16;
            cp16(stb + off, vhb + s);
            cp16(stb + off + G2_AL, vlb + s);
            size_t sB = (size_t)(c20 + r) * 512 + kc * 64 + q * 8;
            cp16(stb + G2_B + off, g_wph + sB);
            cp16(stb + G2_B + off + G2_BL, g_wpl + sB);
        }
        cp_commit();
    };

    issue(0, 0);

    for (int kc = 0; kc < 8; ++kc) {
        const int st = kc & 1;
        cp_wait0();
        __syncthreads();
        if (kc < 7) issue(kc + 1, st ^ 1);
        mma_stage2<4, G2_AL, G2_BL>(sb + st * G2_STG, sb + st * G2_STG, fr, C);
    }
    __syncthreads();

    // epilogue: stage to smem [c2][r] with bias, then coalesced x8 broadcast
    float* Cs = (float*)smem;      // [128][132] floats = 67584 B
    const int gr = lane >> 2, gc2 = (lane & 3) * 2;
    #pragma unroll
    for (int mi = 0; mi < 2; ++mi) {
        int r = mw * 32 + mi * 16 + gr;
        #pragma unroll
        for (int ni = 0; ni < 4; ++ni) {
            int c2l = nw * 32 + ni * 8 + gc2;
            float b0 = __ldg(bp + c20 + c2l), b1 = __ldg(bp + c20 + c2l + 1);
            Cs[c2l * 132 + r]           = C[mi][ni][0] + b0;
            Cs[(c2l + 1) * 132 + r]     = C[mi][ni][1] + b1;
            Cs[c2l * 132 + r + 8]       = C[mi][ni][2] + b0;
            Cs[(c2l + 1) * 132 + r + 8] = C[mi][ni][3] + b1;
        }
    }
    __syncthreads();

    float* ob = out + (size_t)b * (C_DIM * N_DIM) + (size_t)c20 * N_DIM;
    const int f4 = tid & 31, sub = tid >> 5;
    #pragma unroll 4
    for (int i = 0; i < 64; ++i) {
        int rowid = i * 16 + sub;               // 1024 row-writes
        int c2l = rowid >> 3, mrep = rowid & 7;
        float4 v = *(float4*)&Cs[c2l * 132 + f4 * 4];
        *(float4*)(ob + (size_t)c2l * N_DIM + mrep * 128 + f4 * 4) = v;
    }
}

// ---------------------------------------------------------------------------
extern "C" void kernel_launch(void* const* d_in, const int* in_sizes, int n_in,
                              void* d_out, int out_size) {
    const float* x    = (const float*)d_in[0];
    const float* Wqkv = (const float*)d_in[1];
    const float* bqkv = (const float*)d_in[2];
    const float* Wp   = (const float*)d_in[3];
    const float* bp   = (const float*)d_in[4];
    float* out = (float*)d_out;

    cudaFuncSetAttribute(gemm1_mma, cudaFuncAttributeMaxDynamicSharedMemorySize, G1_SMEM);
    cudaFuncSetAttribute(gemm2_mma, cudaFuncAttributeMaxDynamicSharedMemorySize, G2_SMEM);

    prep_all<<<384, 256>>>(Wqkv, bqkv, Wp);
    gemm1_mma<<<dim3(4, B_DIM), 512, G1_SMEM>>>(x);
    gemm2_mma<<<dim3(4, B_DIM), 512, G2_SMEM>>>(bp, out);
}

// round 9
// speedup vs baseline: 1.1127x; 1.1127x over previous
#include <cuda_runtime.h>
#include <cuda_bf16.h>
#include <cstdint>

#define B_DIM 32
#define C_DIM 512
#define N_DIM 1024   // H*W

// ---------------- device scratch (allocation-free) --------------------------
__device__ __align__(16) unsigned short g_wvh[64 * 512];    // Wv^T hi  [d][c]
__device__ __align__(16) unsigned short g_wvl[64 * 512];    // Wv^T lo
__device__ __align__(16) unsigned short g_wph[512 * 512];   // Wp^T hi  [c2][c]
__device__ __align__(16) unsigned short g_wpl[512 * 512];   // Wp^T lo
__device__ float g_bv[64];
__device__ __align__(16) unsigned g_vh[B_DIM * 1024 * 32];  // v hi bf16 pairs [b][n][d/2]
__device__ __align__(16) unsigned g_vl[B_DIM * 1024 * 32];  // v lo
__device__ int g_flag[B_DIM];                               // per-batch producer count

// ---------------- helpers ----------------------------------------------------
__device__ __forceinline__ unsigned smem_u32(const void* p) {
    unsigned a;
    asm("{ .reg .u64 t; cvta.to.shared.u64 t, %1; cvt.u32.u64 %0, t; }" : "=r"(a) : "l"(p));
    return a;
}
__device__ __forceinline__ void ldm_x4(unsigned* d, unsigned addr) {
    asm volatile("ldmatrix.sync.aligned.m8n8.x4.shared.b16 {%0,%1,%2,%3}, [%4];"
                 : "=r"(d[0]), "=r"(d[1]), "=r"(d[2]), "=r"(d[3]) : "r"(addr));
}
__device__ __forceinline__ void mma_bf16(float* c, const unsigned* a, const unsigned* b) {
    asm volatile(
        "mma.sync.aligned.m16n8k16.row.col.f32.bf16.bf16.f32 "
        "{%0,%1,%2,%3}, {%4,%5,%6,%7}, {%8,%9}, {%0,%1,%2,%3};"
        : "+f"(c[0]), "+f"(c[1]), "+f"(c[2]), "+f"(c[3])
        : "r"(a[0]), "r"(a[1]), "r"(a[2]), "r"(a[3]), "r"(b[0]), "r"(b[1]));
}
__device__ __forceinline__ void cp16(unsigned dst, const void* src) {
    asm volatile("cp.async.cg.shared.global [%0], [%1], 16;" :: "r"(dst), "l"(src));
}
__device__ __forceinline__ void cp_commit() { asm volatile("cp.async.commit_group;" ::: "memory"); }
__device__ __forceinline__ void cp_wait0()  { asm volatile("cp.async.wait_group 0;" ::: "memory"); }

__device__ __forceinline__ void cvt_split_pair(float f0, float f1, unsigned& h, unsigned& l) {
    asm("cvt.rn.bf16x2.f32 %0, %1, %2;" : "=r"(h) : "f"(f1), "f"(f0));
    float r0 = f0 - __uint_as_float(h << 16);
    float r1 = f1 - __uint_as_float(h & 0xffff0000u);
    asm("cvt.rn.bf16x2.f32 %0, %1, %2;" : "=r"(l) : "f"(r1), "f"(r0));
}

// ---------------------------------------------------------------------------
// prep (single launch): blocks [0,128) -> Wv^T split + bias; [128,384) -> Wp^T
// Also zeroes the per-batch flags for this replay.
// ---------------------------------------------------------------------------
__global__ void prep_all(const float* __restrict__ Wqkv, const float* __restrict__ bqkv,
                         const float* __restrict__ Wp) {
    int bid = blockIdx.x, tid = threadIdx.x;
    if (bid == 0 && tid < B_DIM) g_flag[tid] = 0;
    if (bid < 128) {
        int idx = bid * 256 + tid;                 // 32768
        int d = idx & 63, c = idx >> 6;
        const float* p = Wqkv + (size_t)c * 1536 + 1024 + d;
        float s = 0.f;
        #pragma unroll
        for (int h = 0; h < 8; ++h) s += p[h * 64];
        s *= 0.125f;
        __nv_bfloat16 hi = __float2bfloat16(s);
        __nv_bfloat16 lo = __float2bfloat16(s - __bfloat162float(hi));
        g_wvh[d * 512 + c] = *(unsigned short*)&hi;
        g_wvl[d * 512 + c] = *(unsigned short*)&lo;
        if (idx < 64) {
            float t = 0.f;
            #pragma unroll
            for (int h = 0; h < 8; ++h) t += bqkv[1024 + h * 64 + idx];
            g_bv[idx] = t * 0.125f;
        }
    } else {
        __shared__ float th[32][33], tl[32][33];
        int t = bid - 128;                          // 256 tiles
        int c0 = (t & 15) * 32, c20 = (t >> 4) * 32;
        int tx = tid & 31, ty = tid >> 5;           // (32, 8)
        #pragma unroll
        for (int i = 0; i < 4; ++i) {
            int c = c0 + ty + i * 8;
            float s = Wp[(size_t)c * 512 + c20 + tx];
            float hi = __bfloat162float(__float2bfloat16(s));
            th[ty + i * 8][tx] = hi;
            tl[ty + i * 8][tx] = s - hi;
        }
        __syncthreads();
        #pragma unroll
        for (int i = 0; i < 4; ++i) {
            int c2 = c20 + ty + i * 8;
            __nv_bfloat16 hb = __float2bfloat16(th[tx][ty + i * 8]);
            __nv_bfloat16 lb = __float2bfloat16(tl[tx][ty + i * 8]);
            g_wph[(size_t)c2 * 512 + c0 + tx] = *(unsigned short*)&hb;
            g_wpl[(size_t)c2 * 512 + c0 + tx] = *(unsigned short*)&lb;
        }
    }
}

// ---------------- warp MMA fragment offsets ----------------------------------
struct Frag { unsigned aoff[2]; unsigned boff[2]; };

template<int PITCHB>
__device__ __forceinline__ Frag make_frag(int lane, int mw, int nw, unsigned off_b) {
    Frag fr;
    const int j4 = lane >> 3, r8 = lane & 7;
    #pragma unroll
    for (int mi = 0; mi < 2; ++mi)
        fr.aoff[mi] = (mw * 32 + mi * 16 + (j4 & 1) * 8 + r8) * PITCHB + (j4 >> 1) * 16;
    const int g2 = (lane >> 4) & 1, c8 = (lane >> 3) & 1;
    #pragma unroll
    for (int j2 = 0; j2 < 2; ++j2)
        fr.boff[j2] = off_b + (nw * 32 + j2 * 16 + g2 * 8 + r8) * PITCHB + c8 * 16;
    return fr;
}

template<int KS, int AL, int BL>
__device__ __forceinline__ void mma_stage(unsigned base, const Frag& fr, float C[2][4][4]) {
    #pragma unroll
    for (int ks = 0; ks < KS; ++ks) {
        unsigned ah[2][4], al[2][4], bh[2][4], bl[2][4];
        #pragma unroll
        for (int mi = 0; mi < 2; ++mi) {
            ldm_x4(ah[mi], base + fr.aoff[mi] + ks * 32);
            ldm_x4(al[mi], base + fr.aoff[mi] + ks * 32 + AL);
        }
        #pragma unroll
        for (int j2 = 0; j2 < 2; ++j2) {
            ldm_x4(bh[j2], base + fr.boff[j2] + ks * 32);
            ldm_x4(bl[j2], base + fr.boff[j2] + ks * 32 + BL);
        }
        #pragma unroll
        for (int mi = 0; mi < 2; ++mi)
            #pragma unroll
            for (int ni = 0; ni < 4; ++ni) {
                const unsigned* bhp = &bh[ni >> 1][(ni & 1) * 2];
                const unsigned* blp = &bl[ni >> 1][(ni & 1) * 2];
                mma_bf16(C[mi][ni], ah[mi], bhp);
                mma_bf16(C[mi][ni], ah[mi], blp);
                mma_bf16(C[mi][ni], al[mi], bhp);
            }
    }
}

// -------------------- GEMM1 body (round-6 config, verbatim) -----------------
// tile 256(n) x 64(d), 16 warps (8m x 2n), K-chunk 32, 16 chunks, 2 stages
// stage: Ah 256*80=20480 | Al | Bh 64*80=5120 | Bl -> 51200
#define G1_AL 20480
#define G1_B  40960
#define G1_BL 5120
#define G1_STG 51200

__device__ __forceinline__ void gemm1_body(const float* __restrict__ x,
                                           char* smem, int b, int n0) {
    const int tid = threadIdx.x, lane = tid & 31, wid = tid >> 5;
    const int mw = wid >> 1, nw = wid & 1;
    const unsigned sb = smem_u32(smem);
    const Frag fr = make_frag<80>(lane, mw, nw, G1_B);

    const int m_ld = tid & 255, kb0 = tid >> 8;
    const float* xb = x + (size_t)b * (C_DIM * N_DIM) + n0;

    float C[2][4][4] = {};
    float f[2][8];

    auto ldg_chunk = [&](int kc) {
        const float* xc = xb + (size_t)kc * 32 * N_DIM;
        #pragma unroll
        for (int i = 0; i < 2; ++i) {
            int k0 = (kb0 + 2 * i) * 8;
            #pragma unroll
            for (int j = 0; j < 8; ++j)
                f[i][j] = xc[(size_t)(k0 + j) * N_DIM + m_ld];
        }
    };
    auto issueB = [&](int kc, int st) {
        int half = tid >> 8, d = (tid & 255) >> 2, q = tid & 3;
        const unsigned short* src = half ? g_wvl : g_wvh;
        size_t s = (size_t)d * 512 + kc * 32 + q * 8;
        cp16(sb + st * G1_STG + G1_B + half * G1_BL + d * 80 + q * 16, src + s);
        cp_commit();
    };
    auto cvt_sts = [&](int st) {
        char* base = smem + st * G1_STG;
        #pragma unroll
        for (int i = 0; i < 2; ++i) {
            unsigned h[4], l[4];
            #pragma unroll
            for (int p = 0; p < 4; ++p)
                cvt_split_pair(f[i][2 * p], f[i][2 * p + 1], h[p], l[p]);
            unsigned off = m_ld * 80 + (kb0 + 2 * i) * 16;
            *(uint4*)(base + off) = make_uint4(h[0], h[1], h[2], h[3]);
            *(uint4*)(base + G1_AL + off) = make_uint4(l[0], l[1], l[2], l[3]);
        }
    };

    ldg_chunk(0);
    issueB(0, 0);
    cvt_sts(0);
    ldg_chunk(1);

    for (int kc = 0; kc < 16; ++kc) {
        const int st = kc & 1, nst = st ^ 1;
        cp_wait0();
        __syncthreads();
        if (kc < 15) { cvt_sts(nst); issueB(kc + 1, nst); }
        if (kc < 14) ldg_chunk(kc + 2);
        mma_stage<2, G1_AL, G1_BL>(sb + st * G1_STG, fr, C);
    }

    // epilogue: add bias, split, store v
    const int gr = lane >> 2, gc2 = (lane & 3) * 2;
    #pragma unroll
    for (int mi = 0; mi < 2; ++mi) {
        int m = n0 + mw * 32 + mi * 16 + gr;
        unsigned base0 = (unsigned)(b * 1024 + m) * 32u;
        unsigned base1 = base0 + 8 * 32;
        #pragma unroll
        for (int ni = 0; ni < 4; ++ni) {
            int d = nw * 32 + ni * 8 + gc2;
            float bv0 = g_bv[d], bv1 = g_bv[d + 1];
            unsigned h, l;
            cvt_split_pair(C[mi][ni][0] + bv0, C[mi][ni][1] + bv1, h, l);
            g_vh[base0 + (d >> 1)] = h;
            g_vl[base0 + (d >> 1)] = l;
            cvt_split_pair(C[mi][ni][2] + bv0, C[mi][ni][3] + bv1, h, l);
            g_vh[base1 + (d >> 1)] = h;
            g_vl[base1 + (d >> 1)] = l;
        }
    }

    // release: make v visible, then bump the per-batch flag
    __threadfence();
    __syncthreads();
    if (tid == 0) atomicAdd(&g_flag[b], 1);
}

// -------------------- GEMM2 body (round-6 config, verbatim) -----------------
// tile 128(r) x 128(c2), 16 warps (4m x 4n), K-chunk 64, 8 chunks, 2 stages
// stage: Ah 128*144=18432 | Al | Bh | Bl -> 73728
#define G2_AL 18432
#define G2_B  36864
#define G2_BL 18432
#define G2_STG 73728

__device__ __forceinline__ void gemm2_body(const float* __restrict__ bp,
                                           float* __restrict__ out,
                                           char* smem, int b, int c20) {
    const int tid = threadIdx.x, lane = tid & 31, wid = tid >> 5;
    const int mw = wid >> 2, nw = wid & 3;
    const unsigned sb = smem_u32(smem);
    const Frag fr = make_frag<144>(lane, mw, nw, G2_B);

    // acquire: wait for all 4 producer CTAs of this batch
    if (tid == 0) {
        while (atomicAdd(&g_flag[b], 0) < 4) __nanosleep(128);
    }
    __syncthreads();
    __threadfence();

    const unsigned short* vhb = (const unsigned short*)g_vh + (size_t)b * 65536;
    const unsigned short* vlb = (const unsigned short*)g_vl + (size_t)b * 65536;

    float C[2][4][4] = {};

    auto issue = [&](int kc, int st) {
        unsigned stb = sb + st * G2_STG;
        #pragma unroll
        for (int i = 0; i < 2; ++i) {
            int idx = tid * 2 + i;                 // 0..1023
            int r = idx >> 3, q = idx & 7;
            size_t s = (size_t)r * 512 + kc * 64 + q * 8;
            unsigned off = r * 144 + q * 16;
            cp16(stb + off, vhb + s);
            cp16(stb + off + G2_AL, vlb + s);
            size_t sB = (size_t)(c20 + r) * 512 + kc * 64 + q * 8;
            cp16(stb + G2_B + off, g_wph + sB);
            cp16(stb + G2_B + off + G2_BL, g_wpl + sB);
        }
        cp_commit();
    };

    issue(0, 0);

    for (int kc = 0; kc < 8; ++kc) {
        const int st = kc & 1;
        cp_wait0();
        __syncthreads();
        if (kc < 7) issue(kc + 1, st ^ 1);
        mma_stage<4, G2_AL, G2_BL>(sb + st * G2_STG, fr, C);
    }
    __syncthreads();

    // epilogue: stage to smem [c2][r] with bias, then coalesced x8 broadcast
    float* Cs = (float*)smem;      // [128][132] floats = 67584 B
    const int gr = lane >> 2, gc2 = (lane & 3) * 2;
    #pragma unroll
    for (int mi = 0; mi < 2; ++mi) {
        int r = mw * 32 + mi * 16 + gr;
        #pragma unroll
        for (int ni = 0; ni < 4; ++ni) {
            int c2l = nw * 32 + ni * 8 + gc2;
            float b0 = __ldg(bp + c20 + c2l), b1 = __ldg(bp + c20 + c2l + 1);
            Cs[c2l * 132 + r]           = C[mi][ni][0] + b0;
            Cs[(c2l + 1) * 132 + r]     = C[mi][ni][1] + b1;
            Cs[c2l * 132 + r + 8]       = C[mi][ni][2] + b0;
            Cs[(c2l + 1) * 132 + r + 8] = C[mi][ni][3] + b1;
        }
    }
    __syncthreads();

    float* ob = out + (size_t)b * (C_DIM * N_DIM) + (size_t)c20 * N_DIM;
    const int f4 = tid & 31, sub = tid >> 5;
    #pragma unroll 4
    for (int i = 0; i < 64; ++i) {
        int rowid = i * 16 + sub;               // 1024 row-writes
        int c2l = rowid >> 3, mrep = rowid & 7;
        float4 v = *(float4*)&Cs[c2l * 132 + f4 * 4];
        *(float4*)(ob + (size_t)c2l * N_DIM + mrep * 128 + f4 * 4) = v;
    }
}

// ---------------------------------------------------------------------------
// Fused kernel: bids [0,128) = gemm1 producers; [128,256) = gemm2 consumers.
// 1 CTA/SM (147456B smem) -> all producers resident in wave 1: no deadlock.
// ---------------------------------------------------------------------------
#define FUSED_SMEM (2 * G2_STG)   // 147456 >= 2*G1_STG (102400)

__global__ void __launch_bounds__(512) fused_mma(const float* __restrict__ x,
                                                 const float* __restrict__ bp,
                                                 float* __restrict__ out) {
    extern __shared__ char smem[];
    const int bid = blockIdx.x;
    if (bid < 128) {
        gemm1_body(x, smem, bid >> 2, (bid & 3) * 256);
    } else {
        const int b2 = bid - 128;
        gemm2_body(bp, out, smem, b2 >> 2, (b2 & 3) * 128);
    }
}

// ---------------------------------------------------------------------------
extern "C" void kernel_launch(void* const* d_in, const int* in_sizes, int n_in,
                              void* d_out, int out_size) {
    const float* x    = (const float*)d_in[0];
    const float* Wqkv = (const float*)d_in[1];
    const float* bqkv = (const float*)d_in[2];
    const float* Wp   = (const float*)d_in[3];
    const float* bp   = (const float*)d_in[4];
    float* out = (float*)d_out;

    cudaFuncSetAttribute(fused_mma, cudaFuncAttributeMaxDynamicSharedMemorySize, FUSED_SMEM);

    prep_all<<<384, 256>>>(Wqkv, bqkv, Wp);
    fused_mma<<<256, 512, FUSED_SMEM>>>(x, bp, out);
}

// round 10
// speedup vs baseline: 1.1647x; 1.0467x over previous
#include <cuda_runtime.h>
#include <cuda_bf16.h>
#include <cstdint>

#define B_DIM 32
#define C_DIM 512
#define N_DIM 1024   // H*W

// ---------------- device scratch (allocation-free) --------------------------
__device__ __align__(16) unsigned short g_wvh[64 * 512];    // Wv^T hi  [d][c]
__device__ __align__(16) unsigned short g_wvl[64 * 512];    // Wv^T lo
__device__ __align__(16) unsigned short g_wph[512 * 512];   // Wp^T hi  [c2][c]
__device__ __align__(16) unsigned short g_wpl[512 * 512];   // Wp^T lo
__device__ float g_bv[64];
__device__ __align__(16) unsigned g_vh[B_DIM * 1024 * 32];  // v hi bf16 pairs [b][n][d/2]
__device__ __align__(16) unsigned g_vl[B_DIM * 1024 * 32];  // v lo
__device__ int g_flag[B_DIM];                               // per-batch producer count

// ---------------- helpers ----------------------------------------------------
__device__ __forceinline__ unsigned smem_u32(const void* p) {
    unsigned a;
    asm("{ .reg .u64 t; cvta.to.shared.u64 t, %1; cvt.u32.u64 %0, t; }" : "=r"(a) : "l"(p));
    return a;
}
__device__ __forceinline__ void ldm_x4(unsigned* d, unsigned addr) {
    asm volatile("ldmatrix.sync.aligned.m8n8.x4.shared.b16 {%0,%1,%2,%3}, [%4];"
                 : "=r"(d[0]), "=r"(d[1]), "=r"(d[2]), "=r"(d[3]) : "r"(addr));
}
__device__ __forceinline__ void mma_bf16(float* c, const unsigned* a, const unsigned* b) {
    asm volatile(
        "mma.sync.aligned.m16n8k16.row.col.f32.bf16.bf16.f32 "
        "{%0,%1,%2,%3}, {%4,%5,%6,%7}, {%8,%9}, {%0,%1,%2,%3};"
        : "+f"(c[0]), "+f"(c[1]), "+f"(c[2]), "+f"(c[3])
        : "r"(a[0]), "r"(a[1]), "r"(a[2]), "r"(a[3]), "r"(b[0]), "r"(b[1]));
}
__device__ __forceinline__ void cp16(unsigned dst, const void* src) {
    asm volatile("cp.async.cg.shared.global [%0], [%1], 16;" :: "r"(dst), "l"(src));
}
__device__ __forceinline__ void cp_commit() { asm volatile("cp.async.commit_group;" ::: "memory"); }
__device__ __forceinline__ void cp_wait0()  { asm volatile("cp.async.wait_group 0;" ::: "memory"); }

__device__ __forceinline__ void cvt_split_pair(float f0, float f1, unsigned& h, unsigned& l) {
    asm("cvt.rn.bf16x2.f32 %0, %1, %2;" : "=r"(h) : "f"(f1), "f"(f0));
    float r0 = f0 - __uint_as_float(h << 16);
    float r1 = f1 - __uint_as_float(h & 0xffff0000u);
    asm("cvt.rn.bf16x2.f32 %0, %1, %2;" : "=r"(l) : "f"(r1), "f"(r0));
}

// ---------------------------------------------------------------------------
// prep (single launch): blocks [0,128) -> Wv^T split + bias; [128,384) -> Wp^T
// Also zeroes per-batch flags for this replay.
// ---------------------------------------------------------------------------
__global__ void prep_all(const float* __restrict__ Wqkv, const float* __restrict__ bqkv,
                         const float* __restrict__ Wp) {
    int bid = blockIdx.x, tid = threadIdx.x;
    if (bid == 0 && tid < B_DIM) g_flag[tid] = 0;
    if (bid < 128) {
        int idx = bid * 256 + tid;                 // 32768
        int d = idx & 63, c = idx >> 6;
        const float* p = Wqkv + (size_t)c * 1536 + 1024 + d;
        float s = 0.f;
        #pragma unroll
        for (int h = 0; h < 8; ++h) s += p[h * 64];
        s *= 0.125f;
        __nv_bfloat16 hi = __float2bfloat16(s);
        __nv_bfloat16 lo = __float2bfloat16(s - __bfloat162float(hi));
        g_wvh[d * 512 + c] = *(unsigned short*)&hi;
        g_wvl[d * 512 + c] = *(unsigned short*)&lo;
        if (idx < 64) {
            float t = 0.f;
            #pragma unroll
            for (int h = 0; h < 8; ++h) t += bqkv[1024 + h * 64 + idx];
            g_bv[idx] = t * 0.125f;
        }
    } else {
        __shared__ float th[32][33], tl[32][33];
        int t = bid - 128;                          // 256 tiles
        int c0 = (t & 15) * 32, c20 = (t >> 4) * 32;
        int tx = tid & 31, ty = tid >> 5;           // (32, 8)
        #pragma unroll
        for (int i = 0; i < 4; ++i) {
            int c = c0 + ty + i * 8;
            float s = Wp[(size_t)c * 512 + c20 + tx];
            float hi = __bfloat162float(__float2bfloat16(s));
            th[ty + i * 8][tx] = hi;
            tl[ty + i * 8][tx] = s - hi;
        }
        __syncthreads();
        #pragma unroll
        for (int i = 0; i < 4; ++i) {
            int c2 = c20 + ty + i * 8;
            __nv_bfloat16 hb = __float2bfloat16(th[tx][ty + i * 8]);
            __nv_bfloat16 lb = __float2bfloat16(tl[tx][ty + i * 8]);
            g_wph[(size_t)c2 * 512 + c0 + tx] = *(unsigned short*)&hb;
            g_wpl[(size_t)c2 * 512 + c0 + tx] = *(unsigned short*)&lb;
        }
    }
}

// ---------------- warp MMA fragment offsets (pitch 80B) ----------------------
struct Frag { unsigned aoff[2]; unsigned boff[2]; };

__device__ __forceinline__ Frag make_frag(int lane, int mw, int nw, unsigned off_b) {
    Frag fr;
    const int j4 = lane >> 3, r8 = lane & 7;
    #pragma unroll
    for (int mi = 0; mi < 2; ++mi)
        fr.aoff[mi] = (mw * 32 + mi * 16 + (j4 & 1) * 8 + r8) * 80 + (j4 >> 1) * 16;
    const int g2 = (lane >> 4) & 1, c8 = (lane >> 3) & 1;
    #pragma unroll
    for (int j2 = 0; j2 < 2; ++j2)
        fr.boff[j2] = off_b + (nw * 32 + j2 * 16 + g2 * 8 + r8) * 80 + c8 * 16;
    return fr;
}

// stage layout (bytes): Ah[128][40]h @0 | Al @10240 | Bh[64][40]h @20480 | Bl @25600
#define G_AL  10240
#define G_B   20480
#define G_BL  5120
#define G_STG 30720
#define FUSED_SMEM (2 * G_STG)   // 61440 -> 2 CTAs/SM

template<int KS>
__device__ __forceinline__ void mma_stage(unsigned base, const Frag& fr, float C[2][4][4]) {
    #pragma unroll
    for (int ks = 0; ks < KS; ++ks) {
        unsigned ah[2][4], al[2][4], bh[2][4], bl[2][4];
        #pragma unroll
        for (int mi = 0; mi < 2; ++mi) {
            ldm_x4(ah[mi], base + fr.aoff[mi] + ks * 32);
            ldm_x4(al[mi], base + fr.aoff[mi] + ks * 32 + G_AL);
        }
        #pragma unroll
        for (int j2 = 0; j2 < 2; ++j2) {
            ldm_x4(bh[j2], base + fr.boff[j2] + ks * 32);
            ldm_x4(bl[j2], base + fr.boff[j2] + ks * 32 + G_BL);
        }
        #pragma unroll
        for (int mi = 0; mi < 2; ++mi)
            #pragma unroll
            for (int ni = 0; ni < 4; ++ni) {
                const unsigned* bhp = &bh[ni >> 1][(ni & 1) * 2];
                const unsigned* blp = &bl[ni >> 1][(ni & 1) * 2];
                mma_bf16(C[mi][ni], ah[mi], bhp);
                mma_bf16(C[mi][ni], ah[mi], blp);
                mma_bf16(C[mi][ni], al[mi], bhp);
            }
    }
}

// -------------------- GEMM1 body: tile 128(n) x 64(d), 8 warps (4m x 2n) ----
__device__ __forceinline__ void gemm1_body(const float* __restrict__ x,
                                           char* smem, int b, int n0) {
    const int tid = threadIdx.x, lane = tid & 31, wid = tid >> 5;
    const int mw = wid >> 1, nw = wid & 1;
    const unsigned sb = smem_u32(smem);
    const Frag fr = make_frag(lane, mw, nw, G_B);

    const int m_ld = tid & 127, kb0 = tid >> 7;    // kblocks kb0 + 2i
    const float* xb = x + (size_t)b * (C_DIM * N_DIM) + n0;

    float C[2][4][4] = {};
    float f[2][8];

    auto ldg_chunk = [&](int kc) {
        const float* xc = xb + (size_t)kc * 32 * N_DIM;
        #pragma unroll
        for (int i = 0; i < 2; ++i) {
            int k0 = (kb0 + 2 * i) * 8;
            #pragma unroll
            for (int j = 0; j < 8; ++j)
                f[i][j] = xc[(size_t)(k0 + j) * N_DIM + m_ld];
        }
    };
    auto issueB = [&](int kc, int st) {
        int r = tid >> 2, q = tid & 3;             // 64 rows x 4 quads
        size_t s = (size_t)r * 512 + kc * 32 + q * 8;
        unsigned dst = sb + st * G_STG + G_B + r * 80 + q * 16;
        cp16(dst, g_wvh + s);
        cp16(dst + G_BL, g_wvl + s);
        cp_commit();
    };
    auto cvt_sts = [&](int st) {
        char* base = smem + st * G_STG;
        #pragma unroll
        for (int i = 0; i < 2; ++i) {
            unsigned h[4], l[4];
            #pragma unroll
            for (int p = 0; p < 4; ++p)
                cvt_split_pair(f[i][2 * p], f[i][2 * p + 1], h[p], l[p]);
            unsigned off = m_ld * 80 + (kb0 + 2 * i) * 16;
            *(uint4*)(base + off) = make_uint4(h[0], h[1], h[2], h[3]);
            *(uint4*)(base + G_AL + off) = make_uint4(l[0], l[1], l[2], l[3]);
        }
    };

    ldg_chunk(0);
    issueB(0, 0);
    cvt_sts(0);
    ldg_chunk(1);

    for (int kc = 0; kc < 16; ++kc) {
        const int st = kc & 1, nst = st ^ 1;
        cp_wait0();
        __syncthreads();
        if (kc < 15) { cvt_sts(nst); issueB(kc + 1, nst); }
        if (kc < 14) ldg_chunk(kc + 2);
        mma_stage<2>(sb + st * G_STG, fr, C);
    }

    // epilogue: add bias, split, store v
    const int gr = lane >> 2, gc2 = (lane & 3) * 2;
    #pragma unroll
    for (int mi = 0; mi < 2; ++mi) {
        int m = n0 + mw * 32 + mi * 16 + gr;
        unsigned base0 = (unsigned)(b * 1024 + m) * 32u;
        unsigned base1 = base0 + 8 * 32;
        #pragma unroll
        for (int ni = 0; ni < 4; ++ni) {
            int d = nw * 32 + ni * 8 + gc2;
            float bv0 = g_bv[d], bv1 = g_bv[d + 1];
            unsigned h, l;
            cvt_split_pair(C[mi][ni][0] + bv0, C[mi][ni][1] + bv1, h, l);
            g_vh[base0 + (d >> 1)] = h;
            g_vl[base0 + (d >> 1)] = l;
            cvt_split_pair(C[mi][ni][2] + bv0, C[mi][ni][3] + bv1, h, l);
            g_vh[base1 + (d >> 1)] = h;
            g_vl[base1 + (d >> 1)] = l;
        }
    }

    __threadfence();
    __syncthreads();
    if (tid == 0) atomicAdd(&g_flag[b], 1);
}

// -------------------- GEMM2 body: tile 128(r) x 64(c2), 8 warps (4m x 2n) ---
__device__ __forceinline__ void gemm2_body(const float* __restrict__ bp,
                                           float* __restrict__ out,
                                           char* smem, int b, int c20) {
    const int tid = threadIdx.x, lane = tid & 31, wid = tid >> 5;
    const int mw = wid >> 1, nw = wid & 1;
    const unsigned sb = smem_u32(smem);
    const Frag fr = make_frag(lane, mw, nw, G_B);

    // acquire: wait for all 8 producer CTAs of this batch
    if (tid == 0) {
        while (atomicAdd(&g_flag[b], 0) < 8) __nanosleep(64);
    }
    __syncthreads();
    __threadfence();

    const unsigned short* vhb = (const unsigned short*)g_vh + (size_t)b * 65536;
    const unsigned short* vlb = (const unsigned short*)g_vl + (size_t)b * 65536;

    float C[2][4][4] = {};

    auto issue = [&](int kc, int st) {
        unsigned stb = sb + st * G_STG;
        #pragma unroll
        for (int i = 0; i < 2; ++i) {
            int idx = tid + i * 256;               // 0..511
            int r = idx >> 2, q = idx & 3;         // 128 rows x 4 quads
            size_t s = (size_t)r * 512 + kc * 32 + q * 8;
            unsigned off = r * 80 + q * 16;
            cp16(stb + off, vhb + s);
            cp16(stb + off + G_AL, vlb + s);
        }
        int r2 = tid >> 2, q2 = tid & 3;           // 64 rows x 4 quads
        size_t sB = (size_t)(c20 + r2) * 512 + kc * 32 + q2 * 8;
        unsigned offB = stb + G_B + r2 * 80 + q2 * 16;
        cp16(offB, g_wph + sB);
        cp16(offB + G_BL, g_wpl + sB);
        cp_commit();
    };

    issue(0, 0);

    for (int kc = 0; kc < 16; ++kc) {
        const int st = kc & 1;
        cp_wait0();
        __syncthreads();
        if (kc < 15) issue(kc + 1, st ^ 1);
        mma_stage<2>(sb + st * G_STG, fr, C);
    }
    __syncthreads();

    // epilogue: stage to smem [c2][r] with bias, then coalesced x8 broadcast
    float* Cs = (float*)smem;      // [64][132] floats = 33792 B <= 61440
    const int gr = lane >> 2, gc2 = (lane & 3) * 2;
    #pragma unroll
    for (int mi = 0; mi < 2; ++mi) {
        int r = mw * 32 + mi * 16 + gr;
        #pragma unroll
        for (int ni = 0; ni < 4; ++ni) {
            int c2l = nw * 32 + ni * 8 + gc2;
            float b0 = __ldg(bp + c20 + c2l), b1 = __ldg(bp + c20 + c2l + 1);
            Cs[c2l * 132 + r]           = C[mi][ni][0] + b0;
            Cs[(c2l + 1) * 132 + r]     = C[mi][ni][1] + b1;
            Cs[c2l * 132 + r + 8]       = C[mi][ni][2] + b0;
            Cs[(c2l + 1) * 132 + r + 8] = C[mi][ni][3] + b1;
        }
    }
    __syncthreads();

    float* ob = out + (size_t)b * (C_DIM * N_DIM) + (size_t)c20 * N_DIM;
    const int f4 = tid & 31, sub = tid >> 5;       // 32 lanes x 8 subs
    #pragma unroll 4
    for (int i = 0; i < 64; ++i) {
        int rowid = i * 8 + sub;                   // 512 row-writes
        int c2l = rowid >> 3, mrep = rowid & 7;
        float4 v = *(float4*)&Cs[c2l * 132 + f4 * 4];
        *(float4*)(ob + (size_t)c2l * N_DIM + mrep * 128 + f4 * 4) = v;
    }
}

// ---------------------------------------------------------------------------
// Persistent fused kernel: 256 CTAs x 256 threads, 2 CTAs/SM (all resident).
// CTA i: produce gemm1 tile (b=i>>3, n0=(i&7)*128), then consume gemm2 tile
// (b=i>>3, c20=(i&7)*64). Producers never wait -> deadlock-free.
// ---------------------------------------------------------------------------
__global__ void __launch_bounds__(256, 2) fused_mma(const float* __restrict__ x,
                                                    const float* __restrict__ bp,
                                                    float* __restrict__ out) {
    extern __shared__ char smem[];
    const int bid = blockIdx.x;
    const int b = bid >> 3, t8 = bid & 7;
    gemm1_body(x, smem, b, t8 * 128);
    gemm2_body(bp, out, smem, b, t8 * 64);
}

// ---------------------------------------------------------------------------
extern "C" void kernel_launch(void* const* d_in, const int* in_sizes, int n_in,
                              void* d_out, int out_size) {
    const float* x    = (const float*)d_in[0];
    const float* Wqkv = (const float*)d_in[1];
    const float* bqkv = (const float*)d_in[2];
    const float* Wp   = (const float*)d_in[3];
    const float* bp   = (const float*)d_in[4];
    float* out = (float*)d_out;

    cudaFuncSetAttribute(fused_mma, cudaFuncAttributeMaxDynamicSharedMemorySize, FUSED_SMEM);

    prep_all<<<384, 256>>>(Wqkv, bqkv, Wp);
    fused_mma<<<256, 256, FUSED_SMEM>>>(x, bp, out);
}